// round 11
// baseline (speedup 1.0000x reference)
#include <cuda_runtime.h>
#include <cuda_fp16.h>
#include <cstdint>

#define NB 4
#define NC 128
#define NN 4096
#define NG 8
#define QSC2 0.12753102f              // (1/sqrt(128)) * log2(e)
#define HPAD 136                      // half stride for fp16 smem tiles (272B)
#define ATILE (128 * HPAD)            // halves per 128x128 tile

// ---------------- scratch (device globals) ----------------------------------
__device__ __half g_q[NB][NN][NC];    // q pre-scaled by QSC2
__device__ __half g_k[NB][NN][NC];
__device__ __half g_v[NB][NN][NC];
__device__ __half g_h2[NB][NN][NC];
__device__ float  g_part[NB * NG][4][2];
__device__ __half g_wqkv_h[3 * NC * NC];  // [o][c]
__device__ __half g_wout_h[NC * NC];

// ---------------- PTX helpers ------------------------------------------------
__device__ __forceinline__ uint32_t smem_to_u32(const void* p) {
    uint32_t a;
    asm("{ .reg .u64 t; cvta.to.shared.u64 t, %1; cvt.u32.u64 %0, t; }"
        : "=r"(a) : "l"(p));
    return a;
}
#define CP16(dst, src) \
    asm volatile("cp.async.cg.shared.global [%0], [%1], 16;" \
                 :: "r"(dst), "l"(src) : "memory")
#define CP_COMMIT() asm volatile("cp.async.commit_group;" ::: "memory")
#define CP_WAIT0()  asm volatile("cp.async.wait_group 0;" ::: "memory")
#define CP_WAIT1()  asm volatile("cp.async.wait_group 1;" ::: "memory")

__device__ __forceinline__ float ex2f(float x) {
    float y;
    asm("ex2.approx.f32 %0, %1;" : "=f"(y) : "f"(x));
    return y;
}
__device__ __forceinline__ void mma_f16(float4& d, uint32_t a0, uint32_t a1,
                                        uint32_t a2, uint32_t a3,
                                        uint32_t b0, uint32_t b1) {
    asm volatile(
        "mma.sync.aligned.m16n8k16.row.col.f32.f16.f16.f32 "
        "{%0,%1,%2,%3},{%4,%5,%6,%7},{%8,%9},{%0,%1,%2,%3};"
        : "+f"(d.x), "+f"(d.y), "+f"(d.z), "+f"(d.w)
        : "r"(a0), "r"(a1), "r"(a2), "r"(a3), "r"(b0), "r"(b1));
}
__device__ __forceinline__ void ldsm4(uint32_t& r0, uint32_t& r1,
                                      uint32_t& r2, uint32_t& r3, uint32_t a) {
    asm volatile("ldmatrix.sync.aligned.m8n8.x4.shared.b16 {%0,%1,%2,%3}, [%4];"
                 : "=r"(r0), "=r"(r1), "=r"(r2), "=r"(r3) : "r"(a));
}
__device__ __forceinline__ void ldsm4t(uint32_t& r0, uint32_t& r1,
                                       uint32_t& r2, uint32_t& r3, uint32_t a) {
    asm volatile("ldmatrix.sync.aligned.m8n8.x4.trans.shared.b16 {%0,%1,%2,%3}, [%4];"
                 : "=r"(r0), "=r"(r1), "=r"(r2), "=r"(r3) : "r"(a));
}

// ---------------- merged: GroupNorm partial stats + weight fp16 convert -------
__global__ void prep_stats_kernel(const float* __restrict__ x,
                                  const float* __restrict__ w_qkv,
                                  const float* __restrict__ w_out) {
    if (blockIdx.x >= 128) {
        int t = (blockIdx.x - 128) * 256 + threadIdx.x;   // 8192 threads
        for (int i = t; i < 3 * NC * NC; i += 8192) g_wqkv_h[i] = __float2half(w_qkv[i]);
        for (int i = t; i < NC * NC; i += 8192)     g_wout_h[i] = __float2half(w_out[i]);
        return;
    }
    int grp = blockIdx.x >> 2, chunk = blockIdx.x & 3;
    int b = grp >> 3, g = grp & 7;
    const float4* p = (const float4*)(x + ((size_t)(b * NC + g * 16 + chunk * 4)) * NN);
    const int n4 = 4 * NN / 4;
    float s = 0.f, ss = 0.f;
    for (int i = threadIdx.x; i < n4; i += 256) {
        float4 v = p[i];
        s  += v.x + v.y + v.z + v.w;
        ss += v.x * v.x + v.y * v.y + v.z * v.z + v.w * v.w;
    }
    __shared__ float rs[8], rss[8];
    for (int off = 16; off; off >>= 1) {
        s  += __shfl_xor_sync(~0u, s, off);
        ss += __shfl_xor_sync(~0u, ss, off);
    }
    if ((threadIdx.x & 31) == 0) { rs[threadIdx.x >> 5] = s; rss[threadIdx.x >> 5] = ss; }
    __syncthreads();
    if (threadIdx.x < 8) {
        s = rs[threadIdx.x]; ss = rss[threadIdx.x];
        for (int off = 4; off; off >>= 1) {
            s  += __shfl_xor_sync(0xff, s, off);
            ss += __shfl_xor_sync(0xff, ss, off);
        }
        if (threadIdx.x == 0) { g_part[grp][chunk][0] = s; g_part[grp][chunk][1] = ss; }
    }
}

// ---------------- fused GroupNorm + QKV projection (fp16 mma) ------------------
// h stored in smem as [c][n] fp16 (no transpose); A-fragments via ldmatrix.trans.
__global__ void __launch_bounds__(256, 1)
nqkv_kernel(const float* __restrict__ x, const float* __restrict__ gn_w,
            const float* __restrict__ gn_b, const float* __restrict__ b_qkv) {
    extern __shared__ __align__(16) char smraw[];
    __half* hs  = (__half*)smraw;          // [128 c][HPAD n]
    __half* w_s = hs + ATILE;              // [384 o][HPAD c]
    __shared__ float sc[128], sh[128], gm[8], gr[8];
    const uint32_t hs_u = smem_to_u32(hs);
    const uint32_t w_su = smem_to_u32(w_s);

    int b = blockIdx.y, nblk = blockIdx.x * 128;
    int tid = threadIdx.x, wid = tid >> 5, lane = tid & 31;
    int g = lane >> 2, tg = lane & 3;
    int i0 = wid * 16;
    int mat = lane >> 3, rr = lane & 7;

    // weight tiles via cp.async (overlaps everything below)
#pragma unroll
    for (int t = 0; t < 24; t++) {
        int idx = tid + t * 256;
        int r = idx >> 4, u = idx & 15;
        CP16(w_su + (uint32_t)(r * HPAD + u * 8) * 2,
             g_wqkv_h + (size_t)r * NC + u * 8);
    }
    CP_COMMIT();

    // finish GroupNorm stats for this batch
    if (tid < 8) {
        float s = 0.f, ss = 0.f;
        for (int c = 0; c < 4; c++) { s += g_part[b * 8 + tid][c][0]; ss += g_part[b * 8 + tid][c][1]; }
        float mean = s * (1.f / 65536.f);
        float var = ss * (1.f / 65536.f) - mean * mean;
        gm[tid] = mean;
        gr[tid] = rsqrtf(var + 1e-5f);
    }
    __syncthreads();
    if (tid < 128) {
        int gg = tid >> 4;
        float w = gn_w[tid], bb = gn_b[tid];
        sc[tid] = gr[gg] * w;
        sh[tid] = bb - gm[gg] * gr[gg] * w;
    }
    __syncthreads();

    // x -> fp16 [c][n] with norm applied (coalesced LDG, conflict-free STS)
    const float* xb = x + (size_t)b * NC * NN;
#pragma unroll
    for (int t = 0; t < 16; t++) {
        int idx = tid + t * 256;
        int c = idx >> 5, n4 = idx & 31;
        float4 v = *(const float4*)(xb + (size_t)c * NN + nblk + n4 * 4);
        float s_ = sc[c], h_ = sh[c];
        __half2 h0 = __floats2half2_rn(v.x * s_ + h_, v.y * s_ + h_);
        __half2 h1 = __floats2half2_rn(v.z * s_ + h_, v.w * s_ + h_);
        uint2 pk = make_uint2(*(uint32_t*)&h0, *(uint32_t*)&h1);
        *(uint2*)(hs + c * HPAD + n4 * 4) = pk;
    }
    CP_WAIT0();
    __syncthreads();

    // resident A-fragments of h via trans-ldmatrix on [c][n]
    uint32_t qa[8][4];
#pragma unroll
    for (int kt = 0; kt < 8; kt++) {
        uint32_t addr = hs_u +
            (uint32_t)((kt * 16 + (mat >> 1) * 8 + rr) * HPAD + i0 + (mat & 1) * 8) * 2;
        ldsm4t(qa[kt][0], qa[kt][1], qa[kt][2], qa[kt][3], addr);
    }

    int n0g = nblk + i0 + g;
#pragma unroll
    for (int ot = 0; ot < 3; ot++) {
        float4 D[16];
#pragma unroll
        for (int j = 0; j < 16; j++) D[j] = make_float4(0.f, 0.f, 0.f, 0.f);
#pragma unroll
        for (int kt = 0; kt < 8; kt++) {
#pragma unroll
            for (int nt = 0; nt < 8; nt++) {
                uint32_t r0, r1, r2, r3;
                ldsm4(r0, r1, r2, r3,
                      w_su + (uint32_t)((ot * 128 + nt * 16 + (lane & 15)) * HPAD +
                                        kt * 16 + ((lane >> 4) << 3)) * 2);
                mma_f16(D[2 * nt],     qa[kt][0], qa[kt][1], qa[kt][2], qa[kt][3], r0, r2);
                mma_f16(D[2 * nt + 1], qa[kt][0], qa[kt][1], qa[kt][2], qa[kt][3], r1, r3);
            }
        }
        __half* dst = (ot == 0) ? &g_q[b][0][0] : (ot == 1) ? &g_k[b][0][0] : &g_v[b][0][0];
        float scale = (ot == 0) ? QSC2 : 1.f;
#pragma unroll
        for (int j = 0; j < 16; j++) {
            int o = (j >> 1) * 16 + (j & 1) * 8 + tg * 2;
            float b0 = b_qkv[ot * 128 + o], b1 = b_qkv[ot * 128 + o + 1];
            *(__half2*)(dst + (size_t)n0g * NC + o) =
                __floats2half2_rn((D[j].x + b0) * scale, (D[j].y + b1) * scale);
            *(__half2*)(dst + (size_t)(n0g + 8) * NC + o) =
                __floats2half2_rn((D[j].z + b0) * scale, (D[j].w + b1) * scale);
        }
    }
}

// ---------------- fp16 mma flash attention (attn4 structure + resident Q) -----
__global__ void __launch_bounds__(256, 1) attn6_kernel() {
    extern __shared__ __align__(16) char smraw[];
    __half* k_s = (__half*)smraw;
    __half* v_s = k_s + ATILE;
    const uint32_t k_su = smem_to_u32(k_s);
    const uint32_t v_su = smem_to_u32(v_s);

    int tid = threadIdx.x, wid = tid >> 5, lane = tid & 31;
    int g = lane >> 2, tg = lane & 3;
    int b = blockIdx.y, iblk = blockIdx.x * 128;
    int i0 = wid * 16;
    int mat = lane >> 3, rr = lane & 7;
    const __half* qg = &g_q[b][0][0];
    const __half* kg = &g_k[b][0][0];
    const __half* vg = &g_v[b][0][0];

    // stage Q through v_s, extract resident A-fragments
#pragma unroll
    for (int t = 0; t < 8; t++) {
        int idx = tid + t * 256;
        int r = idx >> 4, u = idx & 15;
        *(uint4*)(v_s + r * HPAD + u * 8) =
            *(const uint4*)(qg + (size_t)(iblk + r) * NC + u * 8);
    }
    __syncthreads();
    uint32_t qa[8][4];
#pragma unroll
    for (int kt = 0; kt < 8; kt++)
        ldsm4(qa[kt][0], qa[kt][1], qa[kt][2], qa[kt][3],
              v_su + (uint32_t)((i0 + (lane & 15)) * HPAD + kt * 16 + ((lane >> 4) << 3)) * 2);
    __syncthreads();

    // K(0) group, V(0) group
#pragma unroll
    for (int t = 0; t < 8; t++) {
        int idx = tid + t * 256;
        int r = idx >> 4, u = idx & 15;
        CP16(k_su + (uint32_t)(r * HPAD + u * 8) * 2, kg + (size_t)r * NC + u * 8);
    }
    CP_COMMIT();
#pragma unroll
    for (int t = 0; t < 8; t++) {
        int idx = tid + t * 256;
        int r = idx >> 4, u = idx & 15;
        CP16(v_su + (uint32_t)(r * HPAD + u * 8) * 2, vg + (size_t)r * NC + u * 8);
    }
    CP_COMMIT();

    float4 O[16];
#pragma unroll
    for (int j = 0; j < 16; j++) O[j] = make_float4(0.f, 0.f, 0.f, 0.f);
    float lp0 = 0.f, lp1 = 0.f;

    for (int jt = 0; jt < 32; jt++) {
        CP_WAIT1();          // K(jt) landed
        __syncthreads();

        // ---- GEMM1: S = Q K^T ----
        float4 S[16];
#pragma unroll
        for (int j = 0; j < 16; j++) S[j] = make_float4(0.f, 0.f, 0.f, 0.f);
#pragma unroll
        for (int kt = 0; kt < 8; kt++) {
#pragma unroll
            for (int nt = 0; nt < 8; nt++) {
                uint32_t r0, r1, r2, r3;
                ldsm4(r0, r1, r2, r3,
                      k_su + (uint32_t)((nt * 16 + (lane & 15)) * HPAD +
                                        kt * 16 + ((lane >> 4) << 3)) * 2);
                mma_f16(S[2 * nt],     qa[kt][0], qa[kt][1], qa[kt][2], qa[kt][3], r0, r2);
                mma_f16(S[2 * nt + 1], qa[kt][0], qa[kt][1], qa[kt][2], qa[kt][3], r1, r3);
            }
        }

        // ---- softmax: p = exp2(S) (q pre-scaled by log2e/sqrt(C)) ----
        uint32_t ph[8][4];
#pragma unroll
        for (int nt = 0; nt < 16; nt++) {
            float e0 = ex2f(S[nt].x), e1 = ex2f(S[nt].y);
            float e2 = ex2f(S[nt].z), e3 = ex2f(S[nt].w);
            lp0 += e0 + e1;
            lp1 += e2 + e3;
            __half2 lo = __floats2half2_rn(e0, e1);
            __half2 hi = __floats2half2_rn(e2, e3);
            ph[nt >> 1][(nt & 1) * 2 + 0] = *(uint32_t*)&lo;
            ph[nt >> 1][(nt & 1) * 2 + 1] = *(uint32_t*)&hi;
        }
        __syncthreads();     // everyone done reading k_s

        if (jt < 31) {
            const __half* kn = kg + (size_t)(jt + 1) * 128 * NC;
#pragma unroll
            for (int t = 0; t < 8; t++) {
                int idx = tid + t * 256;
                int r = idx >> 4, u = idx & 15;
                CP16(k_su + (uint32_t)(r * HPAD + u * 8) * 2, kn + (size_t)r * NC + u * 8);
            }
        }
        CP_COMMIT();

        CP_WAIT1();          // V(jt) landed
        __syncthreads();

        // ---- GEMM2: O += P V ----
#pragma unroll
        for (int kb = 0; kb < 8; kb++) {
#pragma unroll
            for (int nt2 = 0; nt2 < 8; nt2++) {
                uint32_t addr = v_su +
                    (uint32_t)((16 * kb + (mat & 1) * 8 + rr) * HPAD +
                               16 * nt2 + (mat >> 1) * 8) * 2;
                uint32_t r0, r1, r2, r3;
                ldsm4t(r0, r1, r2, r3, addr);
                mma_f16(O[2 * nt2],     ph[kb][0], ph[kb][1], ph[kb][2], ph[kb][3], r0, r1);
                mma_f16(O[2 * nt2 + 1], ph[kb][0], ph[kb][1], ph[kb][2], ph[kb][3], r2, r3);
            }
        }
        __syncthreads();     // everyone done reading v_s

        if (jt < 31) {
            const __half* vn = vg + (size_t)(jt + 1) * 128 * NC;
#pragma unroll
            for (int t = 0; t < 8; t++) {
                int idx = tid + t * 256;
                int r = idx >> 4, u = idx & 15;
                CP16(v_su + (uint32_t)(r * HPAD + u * 8) * 2, vn + (size_t)r * NC + u * 8);
            }
        }
        CP_COMMIT();
    }

    // ---- row-sum reduce over tg quad, scale, store h2 fp16 [N][C] ----
    lp0 += __shfl_xor_sync(~0u, lp0, 1);
    lp0 += __shfl_xor_sync(~0u, lp0, 2);
    lp1 += __shfl_xor_sync(~0u, lp1, 1);
    lp1 += __shfl_xor_sync(~0u, lp1, 2);
    float inv0 = 1.f / lp0, inv1 = 1.f / lp1;

    __half* h2 = &g_h2[b][0][0];
    int row0 = iblk + i0 + g;
#pragma unroll
    for (int nt = 0; nt < 16; nt++) {
        int c = nt * 8 + tg * 2;
        *(__half2*)(h2 + (size_t)row0 * NC + c) =
            __floats2half2_rn(O[nt].x * inv0, O[nt].y * inv0);
        *(__half2*)(h2 + (size_t)(row0 + 8) * NC + c) =
            __floats2half2_rn(O[nt].z * inv1, O[nt].w * inv1);
    }
}

// ---------------- output projection (fp16 mma) + bias + residual ---------------
__global__ void __launch_bounds__(256, 1)
out_mma(const float* __restrict__ x, const float* __restrict__ b_out,
        float* __restrict__ out) {
    extern __shared__ __align__(16) char smraw[];
    __half* w_s  = (__half*)smraw;            // [128 o][HPAD c]
    __half* h2_s = w_s + ATILE;               // [128 n][HPAD c]
    const uint32_t w_su = smem_to_u32(w_s), h2_su = smem_to_u32(h2_s);

    int nblk = blockIdx.x * 128, b = blockIdx.y;
    int tid = threadIdx.x, wid = tid >> 5, lane = tid & 31;
    int g = lane >> 2, tg = lane & 3;
    int i0 = wid * 16;

#pragma unroll
    for (int t = 0; t < 8; t++) {
        int idx = tid + t * 256;
        int r = idx >> 4, u = idx & 15;
        CP16(w_su + (uint32_t)(r * HPAD + u * 8) * 2, g_wout_h + (size_t)r * NC + u * 8);
        CP16(h2_su + (uint32_t)(r * HPAD + u * 8) * 2, &g_h2[b][nblk + r][u * 8]);
    }
    CP_COMMIT();
    CP_WAIT0();
    __syncthreads();

    float4 D[16];
#pragma unroll
    for (int j = 0; j < 16; j++) D[j] = make_float4(0.f, 0.f, 0.f, 0.f);

#pragma unroll
    for (int kt = 0; kt < 8; kt++) {
        uint32_t a0, a1, a2, a3;
        ldsm4(a0, a1, a2, a3,
              w_su + (uint32_t)((i0 + (lane & 15)) * HPAD + kt * 16 + ((lane >> 4) << 3)) * 2);
#pragma unroll
        for (int nt = 0; nt < 8; nt++) {
            uint32_t r0, r1, r2, r3;
            ldsm4(r0, r1, r2, r3,
                  h2_su + (uint32_t)((nt * 16 + (lane & 15)) * HPAD + kt * 16 + ((lane >> 4) << 3)) * 2);
            mma_f16(D[2 * nt],     a0, a1, a2, a3, r0, r2);
            mma_f16(D[2 * nt + 1], a0, a1, a2, a3, r1, r3);
        }
    }

    int o0 = i0 + g;
    float bo0 = b_out[o0], bo1 = b_out[o0 + 8];
    const float* xr0 = x + ((size_t)(b * NC + o0)) * NN + nblk;
    const float* xr1 = x + ((size_t)(b * NC + o0 + 8)) * NN + nblk;
    float* or0 = out + ((size_t)(b * NC + o0)) * NN + nblk;
    float* or1 = out + ((size_t)(b * NC + o0 + 8)) * NN + nblk;
#pragma unroll
    for (int j = 0; j < 16; j++) {
        int n = (j >> 1) * 16 + (j & 1) * 8 + tg * 2;
        float2 x0 = *(const float2*)(xr0 + n);
        float2 x1 = *(const float2*)(xr1 + n);
        *(float2*)(or0 + n) = make_float2(D[j].x + bo0 + x0.x, D[j].y + bo0 + x0.y);
        *(float2*)(or1 + n) = make_float2(D[j].z + bo1 + x1.x, D[j].w + bo1 + x1.y);
    }
}

// ---------------- launch -----------------------------------------------------
extern "C" void kernel_launch(void* const* d_in, const int* in_sizes, int n_in,
                              void* d_out, int out_size) {
    const float* x     = (const float*)d_in[0];
    const float* gn_w  = (const float*)d_in[1];
    const float* gn_b  = (const float*)d_in[2];
    const float* w_qkv = (const float*)d_in[3];
    const float* b_qkv = (const float*)d_in[4];
    const float* w_out = (const float*)d_in[5];
    const float* b_out = (const float*)d_in[6];
    float* out = (float*)d_out;

    const int TILE = ATILE * 2;               // 34816 B
    const int SMEM_NQKV = 4 * TILE;           // 139264
    const int SMEM_ATT  = 2 * TILE;           // 69632
    const int SMEM_OUT  = 2 * TILE;           // 69632
    cudaFuncSetAttribute(nqkv_kernel, cudaFuncAttributeMaxDynamicSharedMemorySize, SMEM_NQKV);
    cudaFuncSetAttribute(attn6_kernel, cudaFuncAttributeMaxDynamicSharedMemorySize, SMEM_ATT);
    cudaFuncSetAttribute(out_mma, cudaFuncAttributeMaxDynamicSharedMemorySize, SMEM_OUT);

    prep_stats_kernel<<<160, 256>>>(x, w_qkv, w_out);
    nqkv_kernel<<<dim3(32, 4), 256, SMEM_NQKV>>>(x, gn_w, gn_b, b_qkv);
    attn6_kernel<<<dim3(32, 4), 256, SMEM_ATT>>>();
    out_mma<<<dim3(32, 4), 256, SMEM_OUT>>>(x, b_out, out);
}

// round 13
// speedup vs baseline: 1.5493x; 1.5493x over previous
#include <cuda_runtime.h>
#include <cuda_fp16.h>
#include <cstdint>

#define NB 4
#define NC 128
#define NN 4096
#define NG 8
#define QSC2 0.12753102f              // (1/sqrt(128)) * log2(e)
#define HPAD 136                      // half stride for fp16 smem tiles (272B)
#define ATILE (128 * HPAD)            // halves per 128x128 tile

// ---------------- scratch (device globals) ----------------------------------
__device__ __half g_q[NB][NN][NC];    // q pre-scaled by QSC2
__device__ __half g_k[NB][NN][NC];
__device__ __half g_v[NB][NN][NC];
__device__ __half g_h2[NB][NN][NC];
__device__ float  g_part[NB * NG][4][2];
__device__ __half g_wqkv_h[3 * NC * NC];  // [o][c]
__device__ __half g_wout_h[NC * NC];

// ---------------- PTX helpers ------------------------------------------------
__device__ __forceinline__ uint32_t smem_to_u32(const void* p) {
    uint32_t a;
    asm("{ .reg .u64 t; cvta.to.shared.u64 t, %1; cvt.u32.u64 %0, t; }"
        : "=r"(a) : "l"(p));
    return a;
}
#define CP16(dst, src) \
    asm volatile("cp.async.cg.shared.global [%0], [%1], 16;" \
                 :: "r"(dst), "l"(src) : "memory")
#define CP_COMMIT() asm volatile("cp.async.commit_group;" ::: "memory")
#define CP_WAIT0()  asm volatile("cp.async.wait_group 0;" ::: "memory")
#define CP_WAIT1()  asm volatile("cp.async.wait_group 1;" ::: "memory")

__device__ __forceinline__ float ex2f(float x) {
    float y;
    asm("ex2.approx.f32 %0, %1;" : "=f"(y) : "f"(x));
    return y;
}
__device__ __forceinline__ void mma_f16(float4& d, uint32_t a0, uint32_t a1,
                                        uint32_t a2, uint32_t a3,
                                        uint32_t b0, uint32_t b1) {
    asm volatile(
        "mma.sync.aligned.m16n8k16.row.col.f32.f16.f16.f32 "
        "{%0,%1,%2,%3},{%4,%5,%6,%7},{%8,%9},{%0,%1,%2,%3};"
        : "+f"(d.x), "+f"(d.y), "+f"(d.z), "+f"(d.w)
        : "r"(a0), "r"(a1), "r"(a2), "r"(a3), "r"(b0), "r"(b1));
}
__device__ __forceinline__ void ldsm4(uint32_t& r0, uint32_t& r1,
                                      uint32_t& r2, uint32_t& r3, uint32_t a) {
    asm volatile("ldmatrix.sync.aligned.m8n8.x4.shared.b16 {%0,%1,%2,%3}, [%4];"
                 : "=r"(r0), "=r"(r1), "=r"(r2), "=r"(r3) : "r"(a));
}
__device__ __forceinline__ void ldsm4t(uint32_t& r0, uint32_t& r1,
                                       uint32_t& r2, uint32_t& r3, uint32_t a) {
    asm volatile("ldmatrix.sync.aligned.m8n8.x4.trans.shared.b16 {%0,%1,%2,%3}, [%4];"
                 : "=r"(r0), "=r"(r1), "=r"(r2), "=r"(r3) : "r"(a));
}

// ---------------- merged: GroupNorm partial stats + weight fp16 convert -------
__global__ void prep_stats_kernel(const float* __restrict__ x,
                                  const float* __restrict__ w_qkv,
                                  const float* __restrict__ w_out) {
    if (blockIdx.x >= 128) {
        int t = (blockIdx.x - 128) * 256 + threadIdx.x;   // 8192 threads
        for (int i = t; i < 3 * NC * NC; i += 8192) g_wqkv_h[i] = __float2half(w_qkv[i]);
        for (int i = t; i < NC * NC; i += 8192)     g_wout_h[i] = __float2half(w_out[i]);
        return;
    }
    int grp = blockIdx.x >> 2, chunk = blockIdx.x & 3;
    int b = grp >> 3, g = grp & 7;
    const float4* p = (const float4*)(x + ((size_t)(b * NC + g * 16 + chunk * 4)) * NN);
    const int n4 = 4 * NN / 4;
    float s = 0.f, ss = 0.f;
    for (int i = threadIdx.x; i < n4; i += 256) {
        float4 v = p[i];
        s  += v.x + v.y + v.z + v.w;
        ss += v.x * v.x + v.y * v.y + v.z * v.z + v.w * v.w;
    }
    __shared__ float rs[8], rss[8];
    for (int off = 16; off; off >>= 1) {
        s  += __shfl_xor_sync(~0u, s, off);
        ss += __shfl_xor_sync(~0u, ss, off);
    }
    if ((threadIdx.x & 31) == 0) { rs[threadIdx.x >> 5] = s; rss[threadIdx.x >> 5] = ss; }
    __syncthreads();
    if (threadIdx.x < 8) {
        s = rs[threadIdx.x]; ss = rss[threadIdx.x];
        for (int off = 4; off; off >>= 1) {
            s  += __shfl_xor_sync(0xff, s, off);
            ss += __shfl_xor_sync(0xff, ss, off);
        }
        if (threadIdx.x == 0) { g_part[grp][chunk][0] = s; g_part[grp][chunk][1] = ss; }
    }
}

// ---------------- fused GroupNorm + QKV projection (fp16 mma) ------------------
// h stored in smem as [c][n] fp16 (no transpose); A-fragments via ldmatrix.trans.
__global__ void __launch_bounds__(256, 1)
nqkv_kernel(const float* __restrict__ x, const float* __restrict__ gn_w,
            const float* __restrict__ gn_b, const float* __restrict__ b_qkv) {
    extern __shared__ __align__(16) char smraw[];
    __half* hs  = (__half*)smraw;          // [128 c][HPAD n]
    __half* w_s = hs + ATILE;              // [384 o][HPAD c]
    __shared__ float sc[128], sh[128], gm[8], gr[8];
    const uint32_t hs_u = smem_to_u32(hs);
    const uint32_t w_su = smem_to_u32(w_s);

    int b = blockIdx.y, nblk = blockIdx.x * 128;
    int tid = threadIdx.x, wid = tid >> 5, lane = tid & 31;
    int g = lane >> 2, tg = lane & 3;
    int i0 = wid * 16;
    int mat = lane >> 3, rr = lane & 7;

    // weight tiles via cp.async (overlaps everything below)
#pragma unroll
    for (int t = 0; t < 24; t++) {
        int idx = tid + t * 256;
        int r = idx >> 4, u = idx & 15;
        CP16(w_su + (uint32_t)(r * HPAD + u * 8) * 2,
             g_wqkv_h + (size_t)r * NC + u * 8);
    }
    CP_COMMIT();

    // finish GroupNorm stats for this batch
    if (tid < 8) {
        float s = 0.f, ss = 0.f;
        for (int c = 0; c < 4; c++) { s += g_part[b * 8 + tid][c][0]; ss += g_part[b * 8 + tid][c][1]; }
        float mean = s * (1.f / 65536.f);
        float var = ss * (1.f / 65536.f) - mean * mean;
        gm[tid] = mean;
        gr[tid] = rsqrtf(var + 1e-5f);
    }
    __syncthreads();
    if (tid < 128) {
        int gg = tid >> 4;
        float w = gn_w[tid], bb = gn_b[tid];
        sc[tid] = gr[gg] * w;
        sh[tid] = bb - gm[gg] * gr[gg] * w;
    }
    __syncthreads();

    // x -> fp16 [c][n] with norm applied (coalesced LDG, conflict-free STS)
    const float* xb = x + (size_t)b * NC * NN;
#pragma unroll
    for (int t = 0; t < 16; t++) {
        int idx = tid + t * 256;
        int c = idx >> 5, n4 = idx & 31;
        float4 v = *(const float4*)(xb + (size_t)c * NN + nblk + n4 * 4);
        float s_ = sc[c], h_ = sh[c];
        __half2 h0 = __floats2half2_rn(v.x * s_ + h_, v.y * s_ + h_);
        __half2 h1 = __floats2half2_rn(v.z * s_ + h_, v.w * s_ + h_);
        uint2 pk = make_uint2(*(uint32_t*)&h0, *(uint32_t*)&h1);
        *(uint2*)(hs + c * HPAD + n4 * 4) = pk;
    }
    CP_WAIT0();
    __syncthreads();

    // resident A-fragments of h via trans-ldmatrix on [c][n]
    uint32_t qa[8][4];
#pragma unroll
    for (int kt = 0; kt < 8; kt++) {
        uint32_t addr = hs_u +
            (uint32_t)((kt * 16 + (mat >> 1) * 8 + rr) * HPAD + i0 + (mat & 1) * 8) * 2;
        ldsm4t(qa[kt][0], qa[kt][1], qa[kt][2], qa[kt][3], addr);
    }

    int n0g = nblk + i0 + g;
#pragma unroll
    for (int ot = 0; ot < 3; ot++) {
        float4 D[16];
#pragma unroll
        for (int j = 0; j < 16; j++) D[j] = make_float4(0.f, 0.f, 0.f, 0.f);
#pragma unroll
        for (int kt = 0; kt < 8; kt++) {
#pragma unroll
            for (int nt = 0; nt < 8; nt++) {
                uint32_t r0, r1, r2, r3;
                ldsm4(r0, r1, r2, r3,
                      w_su + (uint32_t)((ot * 128 + nt * 16 + (lane & 15)) * HPAD +
                                        kt * 16 + ((lane >> 4) << 3)) * 2);
                mma_f16(D[2 * nt],     qa[kt][0], qa[kt][1], qa[kt][2], qa[kt][3], r0, r2);
                mma_f16(D[2 * nt + 1], qa[kt][0], qa[kt][1], qa[kt][2], qa[kt][3], r1, r3);
            }
        }
        __half* dst = (ot == 0) ? &g_q[b][0][0] : (ot == 1) ? &g_k[b][0][0] : &g_v[b][0][0];
        float scale = (ot == 0) ? QSC2 : 1.f;
#pragma unroll
        for (int j = 0; j < 16; j++) {
            int o = (j >> 1) * 16 + (j & 1) * 8 + tg * 2;
            float b0 = b_qkv[ot * 128 + o], b1 = b_qkv[ot * 128 + o + 1];
            *(__half2*)(dst + (size_t)n0g * NC + o) =
                __floats2half2_rn((D[j].x + b0) * scale, (D[j].y + b1) * scale);
            *(__half2*)(dst + (size_t)(n0g + 8) * NC + o) =
                __floats2half2_rn((D[j].z + b0) * scale, (D[j].w + b1) * scale);
        }
    }
}

// ---------------- fp16 mma flash attention (R8 attn4 structure + ex2) ---------
__global__ void __launch_bounds__(256, 1) attn4_kernel() {
    extern __shared__ __align__(16) char smraw[];
    __half* q_s = (__half*)smraw;             // [128][HPAD]
    __half* k_s = q_s + ATILE;
    __half* v_s = k_s + ATILE;
    const uint32_t q_su = smem_to_u32(q_s);
    const uint32_t k_su = smem_to_u32(k_s);
    const uint32_t v_su = smem_to_u32(v_s);

    int tid = threadIdx.x, wid = tid >> 5, lane = tid & 31;
    int g = lane >> 2, tg = lane & 3;
    int b = blockIdx.y, iblk = blockIdx.x * 128;
    int i0 = wid * 16;
    const __half* qg = &g_q[b][0][0];
    const __half* kg = &g_k[b][0][0];
    const __half* vg = &g_v[b][0][0];

    // Q tile (plain loads)
#pragma unroll
    for (int t = 0; t < 8; t++) {
        int idx = tid + t * 256;
        int r = idx >> 4, u = idx & 15;
        *(uint4*)(q_s + r * HPAD + u * 8) =
            *(const uint4*)(qg + (size_t)(iblk + r) * NC + u * 8);
    }
    // K(0), V(0) via cp.async (two groups)
#pragma unroll
    for (int t = 0; t < 8; t++) {
        int idx = tid + t * 256;
        int r = idx >> 4, u = idx & 15;
        CP16(k_su + (uint32_t)(r * HPAD + u * 8) * 2, kg + (size_t)r * NC + u * 8);
    }
    CP_COMMIT();
#pragma unroll
    for (int t = 0; t < 8; t++) {
        int idx = tid + t * 256;
        int r = idx >> 4, u = idx & 15;
        CP16(v_su + (uint32_t)(r * HPAD + u * 8) * 2, vg + (size_t)r * NC + u * 8);
    }
    CP_COMMIT();

    float4 O[16];
#pragma unroll
    for (int j = 0; j < 16; j++) O[j] = make_float4(0.f, 0.f, 0.f, 0.f);
    float lp0 = 0.f, lp1 = 0.f;

    for (int jt = 0; jt < 32; jt++) {
        CP_WAIT1();          // K(jt) landed
        __syncthreads();

        // ---- GEMM1: S = Q K^T (fp16 m16n8k16) ----
        float4 S[16];
#pragma unroll
        for (int j = 0; j < 16; j++) S[j] = make_float4(0.f, 0.f, 0.f, 0.f);
#pragma unroll
        for (int kt = 0; kt < 8; kt++) {
            uint32_t a0, a1, a2, a3;
            ldsm4(a0, a1, a2, a3,
                  q_su + (uint32_t)((i0 + (lane & 15)) * HPAD + kt * 16 + ((lane >> 4) << 3)) * 2);
#pragma unroll
            for (int nt = 0; nt < 8; nt++) {
                uint32_t r0, r1, r2, r3;
                ldsm4(r0, r1, r2, r3,
                      k_su + (uint32_t)((nt * 16 + (lane & 15)) * HPAD + kt * 16 + ((lane >> 4) << 3)) * 2);
                mma_f16(S[2 * nt],     a0, a1, a2, a3, r0, r2);
                mma_f16(S[2 * nt + 1], a0, a1, a2, a3, r1, r3);
            }
        }

        // ---- softmax: p = exp2(S) (q pre-scaled by log2e/sqrt(C)) ----
        uint32_t ph[8][4];
#pragma unroll
        for (int nt = 0; nt < 16; nt++) {
            float e0 = ex2f(S[nt].x), e1 = ex2f(S[nt].y);
            float e2 = ex2f(S[nt].z), e3 = ex2f(S[nt].w);
            lp0 += e0 + e1;
            lp1 += e2 + e3;
            __half2 lo = __floats2half2_rn(e0, e1);
            __half2 hi = __floats2half2_rn(e2, e3);
            ph[nt >> 1][(nt & 1) * 2 + 0] = *(uint32_t*)&lo;
            ph[nt >> 1][(nt & 1) * 2 + 1] = *(uint32_t*)&hi;
        }
        __syncthreads();     // everyone done reading k_s

        // prefetch K(jt+1)
        if (jt < 31) {
            const __half* kn = kg + (size_t)(jt + 1) * 128 * NC;
#pragma unroll
            for (int t = 0; t < 8; t++) {
                int idx = tid + t * 256;
                int r = idx >> 4, u = idx & 15;
                CP16(k_su + (uint32_t)(r * HPAD + u * 8) * 2, kn + (size_t)r * NC + u * 8);
            }
        }
        CP_COMMIT();

        CP_WAIT1();          // V(jt) landed
        __syncthreads();

        // ---- GEMM2: O += P V (B via ldmatrix.trans) ----
        int mat = lane >> 3, rr = lane & 7;
#pragma unroll
        for (int kb = 0; kb < 8; kb++) {
#pragma unroll
            for (int nt2 = 0; nt2 < 8; nt2++) {
                uint32_t addr = v_su +
                    (uint32_t)((16 * kb + (mat & 1) * 8 + rr) * HPAD +
                               16 * nt2 + (mat >> 1) * 8) * 2;
                uint32_t r0, r1, r2, r3;
                ldsm4t(r0, r1, r2, r3, addr);
                mma_f16(O[2 * nt2],     ph[kb][0], ph[kb][1], ph[kb][2], ph[kb][3], r0, r1);
                mma_f16(O[2 * nt2 + 1], ph[kb][0], ph[kb][1], ph[kb][2], ph[kb][3], r2, r3);
            }
        }
        __syncthreads();     // everyone done reading v_s

        // prefetch V(jt+1)
        if (jt < 31) {
            const __half* vn = vg + (size_t)(jt + 1) * 128 * NC;
#pragma unroll
            for (int t = 0; t < 8; t++) {
                int idx = tid + t * 256;
                int r = idx >> 4, u = idx & 15;
                CP16(v_su + (uint32_t)(r * HPAD + u * 8) * 2, vn + (size_t)r * NC + u * 8);
            }
        }
        CP_COMMIT();
    }

    // ---- row-sum reduce over the tg quad, scale, store h2 fp16 [N][C] ----
    lp0 += __shfl_xor_sync(~0u, lp0, 1);
    lp0 += __shfl_xor_sync(~0u, lp0, 2);
    lp1 += __shfl_xor_sync(~0u, lp1, 1);
    lp1 += __shfl_xor_sync(~0u, lp1, 2);
    float inv0 = 1.f / lp0, inv1 = 1.f / lp1;

    __half* h2 = &g_h2[b][0][0];
    int row0 = iblk + i0 + g;
#pragma unroll
    for (int nt = 0; nt < 16; nt++) {
        int c = nt * 8 + tg * 2;
        *(__half2*)(h2 + (size_t)row0 * NC + c) =
            __floats2half2_rn(O[nt].x * inv0, O[nt].y * inv0);
        *(__half2*)(h2 + (size_t)(row0 + 8) * NC + c) =
            __floats2half2_rn(O[nt].z * inv1, O[nt].w * inv1);
    }
}

// ---------------- output projection (fp16 mma) + bias + residual ---------------
__global__ void __launch_bounds__(256, 1)
out_mma(const float* __restrict__ x, const float* __restrict__ b_out,
        float* __restrict__ out) {
    extern __shared__ __align__(16) char smraw[];
    __half* w_s  = (__half*)smraw;            // [128 o][HPAD c]
    __half* h2_s = w_s + ATILE;               // [128 n][HPAD c]
    const uint32_t w_su = smem_to_u32(w_s), h2_su = smem_to_u32(h2_s);

    int nblk = blockIdx.x * 128, b = blockIdx.y;
    int tid = threadIdx.x, wid = tid >> 5, lane = tid & 31;
    int g = lane >> 2, tg = lane & 3;
    int i0 = wid * 16;

#pragma unroll
    for (int t = 0; t < 8; t++) {
        int idx = tid + t * 256;
        int r = idx >> 4, u = idx & 15;
        CP16(w_su + (uint32_t)(r * HPAD + u * 8) * 2, g_wout_h + (size_t)r * NC + u * 8);
        CP16(h2_su + (uint32_t)(r * HPAD + u * 8) * 2, &g_h2[b][nblk + r][u * 8]);
    }
    CP_COMMIT();
    CP_WAIT0();
    __syncthreads();

    float4 D[16];
#pragma unroll
    for (int j = 0; j < 16; j++) D[j] = make_float4(0.f, 0.f, 0.f, 0.f);

#pragma unroll
    for (int kt = 0; kt < 8; kt++) {
        uint32_t a0, a1, a2, a3;
        ldsm4(a0, a1, a2, a3,
              w_su + (uint32_t)((i0 + (lane & 15)) * HPAD + kt * 16 + ((lane >> 4) << 3)) * 2);
#pragma unroll
        for (int nt = 0; nt < 8; nt++) {
            uint32_t r0, r1, r2, r3;
            ldsm4(r0, r1, r2, r3,
                  h2_su + (uint32_t)((nt * 16 + (lane & 15)) * HPAD + kt * 16 + ((lane >> 4) << 3)) * 2);
            mma_f16(D[2 * nt],     a0, a1, a2, a3, r0, r2);
            mma_f16(D[2 * nt + 1], a0, a1, a2, a3, r1, r3);
        }
    }

    int o0 = i0 + g;
    float bo0 = b_out[o0], bo1 = b_out[o0 + 8];
    const float* xr0 = x + ((size_t)(b * NC + o0)) * NN + nblk;
    const float* xr1 = x + ((size_t)(b * NC + o0 + 8)) * NN + nblk;
    float* or0 = out + ((size_t)(b * NC + o0)) * NN + nblk;
    float* or1 = out + ((size_t)(b * NC + o0 + 8)) * NN + nblk;
#pragma unroll
    for (int j = 0; j < 16; j++) {
        int n = (j >> 1) * 16 + (j & 1) * 8 + tg * 2;
        float2 x0 = *(const float2*)(xr0 + n);
        float2 x1 = *(const float2*)(xr1 + n);
        *(float2*)(or0 + n) = make_float2(D[j].x + bo0 + x0.x, D[j].y + bo0 + x0.y);
        *(float2*)(or1 + n) = make_float2(D[j].z + bo1 + x1.x, D[j].w + bo1 + x1.y);
    }
}

// ---------------- launch -----------------------------------------------------
extern "C" void kernel_launch(void* const* d_in, const int* in_sizes, int n_in,
                              void* d_out, int out_size) {
    const float* x     = (const float*)d_in[0];
    const float* gn_w  = (const float*)d_in[1];
    const float* gn_b  = (const float*)d_in[2];
    const float* w_qkv = (const float*)d_in[3];
    const float* b_qkv = (const float*)d_in[4];
    const float* w_out = (const float*)d_in[5];
    const float* b_out = (const float*)d_in[6];
    float* out = (float*)d_out;

    const int TILE = ATILE * 2;               // 34816 B
    const int SMEM_NQKV = 4 * TILE;           // 139264
    const int SMEM_ATT  = 3 * TILE;           // 104448
    const int SMEM_OUT  = 2 * TILE;           // 69632
    cudaFuncSetAttribute(nqkv_kernel, cudaFuncAttributeMaxDynamicSharedMemorySize, SMEM_NQKV);
    cudaFuncSetAttribute(attn4_kernel, cudaFuncAttributeMaxDynamicSharedMemorySize, SMEM_ATT);
    cudaFuncSetAttribute(out_mma, cudaFuncAttributeMaxDynamicSharedMemorySize, SMEM_OUT);

    prep_stats_kernel<<<160, 256>>>(x, w_qkv, w_out);
    nqkv_kernel<<<dim3(32, 4), 256, SMEM_NQKV>>>(x, gn_w, gn_b, b_qkv);
    attn4_kernel<<<dim3(32, 4), 256, SMEM_ATT>>>();
    out_mma<<<dim3(32, 4), 256, SMEM_OUT>>>(x, b_out, out);
}